// round 15
// baseline (speedup 1.0000x reference)
#include <cuda_runtime.h>

// Problem constants
#define Bsz 512
#define Tn  48
#define Dn  128
#define Fn  16
#define Hn  512
#define DF  2048      // Dn*Fn
#define NG  2048      // 4*Hn
#define MBIG (Bsz*Tn) // 24576

// ---------------- device scratch (static, allowed) ----------------
__device__ float g_a[Bsz * Dn];                       // attention weights (constant over t)
__device__ float g_G[(size_t)MBIG * NG];              // precomputed input gates [t*Bsz+b][n], ~201MB
__device__ float g_gates[Bsz * NG];                   // per-step gates scratch
__device__ float g_h[Bsz * Hn];
__device__ float g_c[Bsz * Hn];

// ---------------- kernel 0: zero h, c ----------------
__global__ void k_zero() {
    int i = blockIdx.x * blockDim.x + threadIdx.x;
    if (i < Bsz * Hn) { g_h[i] = 0.f; g_c[i] = 0.f; }
}

// ---------------- kernel 1: a[b,d] = softmax_d( sum_{t,f} x[b,t,d,f] * w_x[f*T+t] ) ----------
// (attn_b and the recurrent scalar shifts are softmax-invariant -> dropped)
__global__ void k_softmax(const float* __restrict__ x, const float* __restrict__ attn_w) {
    __shared__ float w_s[Fn * Tn];   // 768
    __shared__ float red[Dn];
    int b = blockIdx.x;
    int d = threadIdx.x;             // 0..127

    for (int i = d; i < Fn * Tn; i += Dn) w_s[i] = attn_w[2 * Hn + i];
    __syncthreads();

    const float4* p = (const float4*)(x + ((size_t)b * Tn) * DF + d * Fn);
    float acc = 0.f;
    #pragma unroll 4
    for (int t = 0; t < Tn; t++) {
        float4 v0 = p[0], v1 = p[1], v2 = p[2], v3 = p[3];
        acc += v0.x * w_s[t]       + v0.y * w_s[48 + t]  + v0.z * w_s[96 + t]  + v0.w * w_s[144 + t]
             + v1.x * w_s[192 + t] + v1.y * w_s[240 + t] + v1.z * w_s[288 + t] + v1.w * w_s[336 + t]
             + v2.x * w_s[384 + t] + v2.y * w_s[432 + t] + v2.z * w_s[480 + t] + v2.w * w_s[528 + t]
             + v3.x * w_s[576 + t] + v3.y * w_s[624 + t] + v3.z * w_s[672 + t] + v3.w * w_s[720 + t];
        p += DF / 4;  // next t
    }

    // block softmax over 128 values
    red[d] = acc; __syncthreads();
    #pragma unroll
    for (int s = 64; s > 0; s >>= 1) {
        if (d < s) red[d] = fmaxf(red[d], red[d + s]);
        __syncthreads();
    }
    float mx = red[0]; __syncthreads();
    float e = expf(acc - mx);
    red[d] = e; __syncthreads();
    #pragma unroll
    for (int s = 64; s > 0; s >>= 1) {
        if (d < s) red[d] += red[d + s];
        __syncthreads();
    }
    g_a[b * Dn + d] = e / red[0];
}

// ---------------- kernel 2: big GEMM  G[m][n] = sum_k (a[b,k/16]*x[b,t,k]) * w_ih[n][k] + bias[n]
// m = t*Bsz + b  (so G is [T][B][NG], contiguous per step for the recurrence)
// 128x128 tile, BK=16, 256 threads, 8x8 per-thread microtile, fp32.
__global__ void __launch_bounds__(256, 2) k_gemm_big(
        const float* __restrict__ x, const float* __restrict__ w_ih,
        const float* __restrict__ b_ih, const float* __restrict__ b_hh) {
    __shared__ float As[16][132];
    __shared__ float Bs[16][132];

    int tid = threadIdx.x;
    int tx = tid & 15, ty = tid >> 4;
    int bm = blockIdx.y, bn = blockIdx.x;

    float acc[8][8];
    #pragma unroll
    for (int i = 0; i < 8; i++)
        #pragma unroll
        for (int j = 0; j < 8; j++) acc[i][j] = 0.f;

    int lin0 = tid * 4;

    for (int k0 = 0; k0 < DF; k0 += 16) {
        #pragma unroll
        for (int r = 0; r < 2; r++) {
            int linear = r * 1024 + lin0;      // 0..2044
            int mi = linear >> 4;              // row within tile (0..127)
            int ki = linear & 15;              // 0,4,8,12
            // A: x_hat row m = bm*128+mi  -> (b, t) gather, contiguous in k
            int m = bm * 128 + mi;
            int bb = m & 511, tt = m >> 9;
            float4 v = *(const float4*)(x + ((size_t)bb * Tn + tt) * DF + k0 + ki);
            float av = g_a[(bb << 7) + ((k0 + ki) >> 4)];   // a[b, d], d = k/16 (const over float4)
            As[ki + 0][mi] = v.x * av;
            As[ki + 1][mi] = v.y * av;
            As[ki + 2][mi] = v.z * av;
            As[ki + 3][mi] = v.w * av;
            // B: w_ih row n = bn*128+mi
            float4 w = *(const float4*)(w_ih + (size_t)(bn * 128 + mi) * DF + k0 + ki);
            Bs[ki + 0][mi] = w.x;
            Bs[ki + 1][mi] = w.y;
            Bs[ki + 2][mi] = w.z;
            Bs[ki + 3][mi] = w.w;
        }
        __syncthreads();

        #pragma unroll
        for (int kk = 0; kk < 16; kk++) {
            float4 a0 = *(const float4*)&As[kk][ty * 8];
            float4 a1 = *(const float4*)&As[kk][ty * 8 + 4];
            float4 b0 = *(const float4*)&Bs[kk][tx * 8];
            float4 b1 = *(const float4*)&Bs[kk][tx * 8 + 4];
            float af[8] = {a0.x, a0.y, a0.z, a0.w, a1.x, a1.y, a1.z, a1.w};
            float bf[8] = {b0.x, b0.y, b0.z, b0.w, b1.x, b1.y, b1.z, b1.w};
            #pragma unroll
            for (int i = 0; i < 8; i++)
                #pragma unroll
                for (int j = 0; j < 8; j++)
                    acc[i][j] += af[i] * bf[j];
        }
        __syncthreads();
    }

    // epilogue: + (b_ih + b_hh)
    int n0 = bn * 128 + tx * 8;
    float4 bi0 = *(const float4*)(b_ih + n0);
    float4 bi1 = *(const float4*)(b_ih + n0 + 4);
    float4 bh0 = *(const float4*)(b_hh + n0);
    float4 bh1 = *(const float4*)(b_hh + n0 + 4);
    float bias[8] = {bi0.x + bh0.x, bi0.y + bh0.y, bi0.z + bh0.z, bi0.w + bh0.w,
                     bi1.x + bh1.x, bi1.y + bh1.y, bi1.z + bh1.z, bi1.w + bh1.w};
    #pragma unroll
    for (int i = 0; i < 8; i++) {
        size_t m = (size_t)bm * 128 + ty * 8 + i;
        float4 o0 = make_float4(acc[i][0] + bias[0], acc[i][1] + bias[1],
                                acc[i][2] + bias[2], acc[i][3] + bias[3]);
        float4 o1 = make_float4(acc[i][4] + bias[4], acc[i][5] + bias[5],
                                acc[i][6] + bias[6], acc[i][7] + bias[7]);
        *(float4*)(g_G + m * NG + n0)     = o0;
        *(float4*)(g_G + m * NG + n0 + 4) = o1;
    }
}

// ---------------- kernel 3: per-step recurrent GEMM: gates = G[t] + h @ w_hh^T
// M=512(b), N=2048(n), K=512. 64x64 tile, BK=16, 256 threads, 4x4 per thread.
__global__ void __launch_bounds__(256) k_gemm_rec(const float* __restrict__ w_hh, int t) {
    __shared__ float As[16][68];
    __shared__ float Bs[16][68];

    int tid = threadIdx.x;
    int tx = tid & 15, ty = tid >> 4;
    int bm = blockIdx.y, bn = blockIdx.x;

    float acc[4][4];
    #pragma unroll
    for (int i = 0; i < 4; i++)
        #pragma unroll
        for (int j = 0; j < 4; j++) acc[i][j] = 0.f;

    int mi = tid >> 2;             // 0..63
    int ki = (tid & 3) * 4;        // 0,4,8,12

    for (int k0 = 0; k0 < Hn; k0 += 16) {
        float4 v = *(const float4*)(g_h + (bm * 64 + mi) * Hn + k0 + ki);
        As[ki + 0][mi] = v.x; As[ki + 1][mi] = v.y; As[ki + 2][mi] = v.z; As[ki + 3][mi] = v.w;
        float4 w = *(const float4*)(w_hh + (size_t)(bn * 64 + mi) * Hn + k0 + ki);
        Bs[ki + 0][mi] = w.x; Bs[ki + 1][mi] = w.y; Bs[ki + 2][mi] = w.z; Bs[ki + 3][mi] = w.w;
        __syncthreads();

        #pragma unroll
        for (int kk = 0; kk < 16; kk++) {
            float4 a = *(const float4*)&As[kk][ty * 4];
            float4 b = *(const float4*)&Bs[kk][tx * 4];
            float af[4] = {a.x, a.y, a.z, a.w};
            float bf[4] = {b.x, b.y, b.z, b.w};
            #pragma unroll
            for (int i = 0; i < 4; i++)
                #pragma unroll
                for (int j = 0; j < 4; j++)
                    acc[i][j] += af[i] * bf[j];
        }
        __syncthreads();
    }

    int n0 = bn * 64 + tx * 4;
    #pragma unroll
    for (int i = 0; i < 4; i++) {
        int b = bm * 64 + ty * 4 + i;
        float4 g = *(const float4*)(g_G + ((size_t)t * Bsz + b) * NG + n0);
        float4 o = make_float4(acc[i][0] + g.x, acc[i][1] + g.y,
                               acc[i][2] + g.z, acc[i][3] + g.w);
        *(float4*)(g_gates + (size_t)b * NG + n0) = o;
    }
}

// ---------------- kernel 4: pointwise LSTM update + output write ----------------
__global__ void k_lstm(float* __restrict__ out, int t) {
    int idx = blockIdx.x * blockDim.x + threadIdx.x;  // 0..262143
    int b = idx >> 9, j = idx & 511;
    const float* gr = g_gates + (size_t)b * NG;
    float gi = gr[j];
    float gf = gr[j + 512];
    float gg = gr[j + 1024];
    float go = gr[j + 1536];
    float c  = g_c[idx];
    float si = 1.f / (1.f + expf(-gi));
    float sf = 1.f / (1.f + expf(-gf));
    float so = 1.f / (1.f + expf(-go));
    float cn = sf * c + si * tanhf(gg);
    float hn = so * tanhf(cn);
    g_c[idx] = cn;
    g_h[idx] = hn;
    out[((size_t)b * Tn + t) * Hn + j] = hn;
}

// ---------------- launch ----------------
extern "C" void kernel_launch(void* const* d_in, const int* in_sizes, int n_in,
                              void* d_out, int out_size) {
    const float* input  = (const float*)d_in[0];  // (B,T,D,F)
    const float* attn_w = (const float*)d_in[1];  // (2H + F*T,)
    // d_in[2] = attn_b : softmax-invariant, unused
    const float* w_ih   = (const float*)d_in[3];  // (4H, D*F)
    const float* w_hh   = (const float*)d_in[4];  // (4H, H)
    const float* b_ih   = (const float*)d_in[5];
    const float* b_hh   = (const float*)d_in[6];
    float* out = (float*)d_out;                   // (B, T, H)

    k_zero<<<(Bsz * Hn + 255) / 256, 256>>>();
    k_softmax<<<Bsz, Dn>>>(input, attn_w);
    k_gemm_big<<<dim3(NG / 128, MBIG / 128), 256>>>(input, w_ih, b_ih, b_hh);

    for (int t = 0; t < Tn; t++) {
        k_gemm_rec<<<dim3(NG / 64, Bsz / 64), 256>>>(w_hh, t);
        k_lstm<<<(Bsz * Hn) / 256, 256>>>(out, t);
    }
}

// round 16
// speedup vs baseline: 1.0078x; 1.0078x over previous
#include <cuda_runtime.h>

// Problem constants
#define Bsz 512
#define Tn  48
#define Dn  128
#define Fn  16
#define Hn  512
#define DF  2048      // Dn*Fn
#define NG  2048      // 4*Hn
#define MBIG (Bsz*Tn) // 24576

// ---------------- device scratch (static, allowed) ----------------
__device__ float g_a[Bsz * Dn];                       // attention weights (constant over t)
__device__ float g_G[(size_t)MBIG * NG];              // precomputed input gates [t*Bsz+b][n], ~201MB
__device__ float g_gates[Bsz * NG];                   // per-step gates scratch
__device__ float g_h[Bsz * Hn];
__device__ float g_c[Bsz * Hn];

// ---------------- kernel 0: zero h, c ----------------
__global__ void k_zero() {
    int i = blockIdx.x * blockDim.x + threadIdx.x;
    if (i < Bsz * Hn) { g_h[i] = 0.f; g_c[i] = 0.f; }
}

// ---------------- kernel 1: a[b,d] = softmax_d( sum_{t,f} x[b,t,d,f] * w_x[f*T+t] ) ----------
// (attn_b and the recurrent scalar shifts are softmax-invariant -> dropped)
__global__ void k_softmax(const float* __restrict__ x, const float* __restrict__ attn_w) {
    __shared__ float w_s[Fn * Tn];   // 768
    __shared__ float red[Dn];
    int b = blockIdx.x;
    int d = threadIdx.x;             // 0..127

    for (int i = d; i < Fn * Tn; i += Dn) w_s[i] = attn_w[2 * Hn + i];
    __syncthreads();

    const float4* p = (const float4*)(x + ((size_t)b * Tn) * DF + d * Fn);
    float acc = 0.f;
    #pragma unroll 4
    for (int t = 0; t < Tn; t++) {
        float4 v0 = p[0], v1 = p[1], v2 = p[2], v3 = p[3];
        acc += v0.x * w_s[t]       + v0.y * w_s[48 + t]  + v0.z * w_s[96 + t]  + v0.w * w_s[144 + t]
             + v1.x * w_s[192 + t] + v1.y * w_s[240 + t] + v1.z * w_s[288 + t] + v1.w * w_s[336 + t]
             + v2.x * w_s[384 + t] + v2.y * w_s[432 + t] + v2.z * w_s[480 + t] + v2.w * w_s[528 + t]
             + v3.x * w_s[576 + t] + v3.y * w_s[624 + t] + v3.z * w_s[672 + t] + v3.w * w_s[720 + t];
        p += DF / 4;  // next t
    }

    // block softmax over 128 values
    red[d] = acc; __syncthreads();
    #pragma unroll
    for (int s = 64; s > 0; s >>= 1) {
        if (d < s) red[d] = fmaxf(red[d], red[d + s]);
        __syncthreads();
    }
    float mx = red[0]; __syncthreads();
    float e = expf(acc - mx);
    red[d] = e; __syncthreads();
    #pragma unroll
    for (int s = 64; s > 0; s >>= 1) {
        if (d < s) red[d] += red[d + s];
        __syncthreads();
    }
    g_a[b * Dn + d] = e / red[0];
}

// ---------------- kernel 2: big GEMM  G[m][n] = sum_k (a[b,k/16]*x[b,t,k]) * w_ih[n][k] + bias[n]
// m = t*Bsz + b  (so G is [T][B][NG], contiguous per step for the recurrence)
// 128x128 tile, BK=16, 256 threads, 8x8 per-thread microtile, fp32.
__global__ void __launch_bounds__(256, 2) k_gemm_big(
        const float* __restrict__ x, const float* __restrict__ w_ih,
        const float* __restrict__ b_ih, const float* __restrict__ b_hh) {
    __shared__ float As[16][132];
    __shared__ float Bs[16][132];

    int tid = threadIdx.x;
    int tx = tid & 15, ty = tid >> 4;
    int bm = blockIdx.y, bn = blockIdx.x;

    float acc[8][8];
    #pragma unroll
    for (int i = 0; i < 8; i++)
        #pragma unroll
        for (int j = 0; j < 8; j++) acc[i][j] = 0.f;

    int lin0 = tid * 4;

    for (int k0 = 0; k0 < DF; k0 += 16) {
        #pragma unroll
        for (int r = 0; r < 2; r++) {
            int linear = r * 1024 + lin0;      // 0..2044
            int mi = linear >> 4;              // row within tile (0..127)
            int ki = linear & 15;              // 0,4,8,12
            // A: x_hat row m = bm*128+mi  -> (b, t) gather, contiguous in k
            int m = bm * 128 + mi;
            int bb = m & 511, tt = m >> 9;
            float4 v = *(const float4*)(x + ((size_t)bb * Tn + tt) * DF + k0 + ki);
            float av = g_a[(bb << 7) + ((k0 + ki) >> 4)];   // a[b, d], d = k/16 (const over float4)
            As[ki + 0][mi] = v.x * av;
            As[ki + 1][mi] = v.y * av;
            As[ki + 2][mi] = v.z * av;
            As[ki + 3][mi] = v.w * av;
            // B: w_ih row n = bn*128+mi
            float4 w = *(const float4*)(w_ih + (size_t)(bn * 128 + mi) * DF + k0 + ki);
            Bs[ki + 0][mi] = w.x;
            Bs[ki + 1][mi] = w.y;
            Bs[ki + 2][mi] = w.z;
            Bs[ki + 3][mi] = w.w;
        }
        __syncthreads();

        #pragma unroll
        for (int kk = 0; kk < 16; kk++) {
            float4 a0 = *(const float4*)&As[kk][ty * 8];
            float4 a1 = *(const float4*)&As[kk][ty * 8 + 4];
            float4 b0 = *(const float4*)&Bs[kk][tx * 8];
            float4 b1 = *(const float4*)&Bs[kk][tx * 8 + 4];
            float af[8] = {a0.x, a0.y, a0.z, a0.w, a1.x, a1.y, a1.z, a1.w};
            float bf[8] = {b0.x, b0.y, b0.z, b0.w, b1.x, b1.y, b1.z, b1.w};
            #pragma unroll
            for (int i = 0; i < 8; i++)
                #pragma unroll
                for (int j = 0; j < 8; j++)
                    acc[i][j] += af[i] * bf[j];
        }
        __syncthreads();
    }

    // epilogue: + (b_ih + b_hh)
    int n0 = bn * 128 + tx * 8;
    float4 bi0 = *(const float4*)(b_ih + n0);
    float4 bi1 = *(const float4*)(b_ih + n0 + 4);
    float4 bh0 = *(const float4*)(b_hh + n0);
    float4 bh1 = *(const float4*)(b_hh + n0 + 4);
    float bias[8] = {bi0.x + bh0.x, bi0.y + bh0.y, bi0.z + bh0.z, bi0.w + bh0.w,
                     bi1.x + bh1.x, bi1.y + bh1.y, bi1.z + bh1.z, bi1.w + bh1.w};
    #pragma unroll
    for (int i = 0; i < 8; i++) {
        size_t m = (size_t)bm * 128 + ty * 8 + i;
        float4 o0 = make_float4(acc[i][0] + bias[0], acc[i][1] + bias[1],
                                acc[i][2] + bias[2], acc[i][3] + bias[3]);
        float4 o1 = make_float4(acc[i][4] + bias[4], acc[i][5] + bias[5],
                                acc[i][6] + bias[6], acc[i][7] + bias[7]);
        *(float4*)(g_G + m * NG + n0)     = o0;
        *(float4*)(g_G + m * NG + n0 + 4) = o1;
    }
}

// ---------------- kernel 3: per-step recurrent GEMM: gates = G[t] + h @ w_hh^T
// M=512(b), N=2048(n), K=512. 64x64 tile, BK=16, 256 threads, 4x4 per thread.
__global__ void __launch_bounds__(256) k_gemm_rec(const float* __restrict__ w_hh, int t) {
    __shared__ float As[16][68];
    __shared__ float Bs[16][68];

    int tid = threadIdx.x;
    int tx = tid & 15, ty = tid >> 4;
    int bm = blockIdx.y, bn = blockIdx.x;

    float acc[4][4];
    #pragma unroll
    for (int i = 0; i < 4; i++)
        #pragma unroll
        for (int j = 0; j < 4; j++) acc[i][j] = 0.f;

    int mi = tid >> 2;             // 0..63
    int ki = (tid & 3) * 4;        // 0,4,8,12

    for (int k0 = 0; k0 < Hn; k0 += 16) {
        float4 v = *(const float4*)(g_h + (bm * 64 + mi) * Hn + k0 + ki);
        As[ki + 0][mi] = v.x; As[ki + 1][mi] = v.y; As[ki + 2][mi] = v.z; As[ki + 3][mi] = v.w;
        float4 w = *(const float4*)(w_hh + (size_t)(bn * 64 + mi) * Hn + k0 + ki);
        Bs[ki + 0][mi] = w.x; Bs[ki + 1][mi] = w.y; Bs[ki + 2][mi] = w.z; Bs[ki + 3][mi] = w.w;
        __syncthreads();

        #pragma unroll
        for (int kk = 0; kk < 16; kk++) {
            float4 a = *(const float4*)&As[kk][ty * 4];
            float4 b = *(const float4*)&Bs[kk][tx * 4];
            float af[4] = {a.x, a.y, a.z, a.w};
            float bf[4] = {b.x, b.y, b.z, b.w};
            #pragma unroll
            for (int i = 0; i < 4; i++)
                #pragma unroll
                for (int j = 0; j < 4; j++)
                    acc[i][j] += af[i] * bf[j];
        }
        __syncthreads();
    }

    int n0 = bn * 64 + tx * 4;
    #pragma unroll
    for (int i = 0; i < 4; i++) {
        int b = bm * 64 + ty * 4 + i;
        float4 g = *(const float4*)(g_G + ((size_t)t * Bsz + b) * NG + n0);
        float4 o = make_float4(acc[i][0] + g.x, acc[i][1] + g.y,
                               acc[i][2] + g.z, acc[i][3] + g.w);
        *(float4*)(g_gates + (size_t)b * NG + n0) = o;
    }
}

// ---------------- kernel 4: pointwise LSTM update + output write ----------------
__global__ void k_lstm(float* __restrict__ out, int t) {
    int idx = blockIdx.x * blockDim.x + threadIdx.x;  // 0..262143
    int b = idx >> 9, j = idx & 511;
    const float* gr = g_gates + (size_t)b * NG;
    float gi = gr[j];
    float gf = gr[j + 512];
    float gg = gr[j + 1024];
    float go = gr[j + 1536];
    float c  = g_c[idx];
    float si = 1.f / (1.f + expf(-gi));
    float sf = 1.f / (1.f + expf(-gf));
    float so = 1.f / (1.f + expf(-go));
    float cn = sf * c + si * tanhf(gg);
    float hn = so * tanhf(cn);
    g_c[idx] = cn;
    g_h[idx] = hn;
    out[((size_t)b * Tn + t) * Hn + j] = hn;
}

// ---------------- launch ----------------
extern "C" void kernel_launch(void* const* d_in, const int* in_sizes, int n_in,
                              void* d_out, int out_size) {
    const float* input  = (const float*)d_in[0];  // (B,T,D,F)
    const float* attn_w = (const float*)d_in[1];  // (2H + F*T,)
    // d_in[2] = attn_b : softmax-invariant, unused
    const float* w_ih   = (const float*)d_in[3];  // (4H, D*F)
    const float* w_hh   = (const float*)d_in[4];  // (4H, H)
    const float* b_ih   = (const float*)d_in[5];
    const float* b_hh   = (const float*)d_in[6];
    float* out = (float*)d_out;                   // (B, T, H)

    k_zero<<<(Bsz * Hn + 255) / 256, 256>>>();
    k_softmax<<<Bsz, Dn>>>(input, attn_w);
    k_gemm_big<<<dim3(NG / 128, MBIG / 128), 256>>>(input, w_ih, b_ih, b_hh);

    for (int t = 0; t < Tn; t++) {
        k_gemm_rec<<<dim3(NG / 64, Bsz / 64), 256>>>(w_hh, t);
        k_lstm<<<(Bsz * Hn) / 256, 256>>>(out, t);
    }
}

// round 17
// speedup vs baseline: 1.0148x; 1.0069x over previous
#include <cuda_runtime.h>

// Problem constants
#define Bsz 512
#define Tn  48
#define Dn  128
#define Fn  16
#define Hn  512
#define DF  2048      // Dn*Fn
#define NG  2048      // 4*Hn
#define MBIG (Bsz*Tn) // 24576

// ---------------- device scratch (static, allowed) ----------------
__device__ float g_a[Bsz * Dn];                       // attention weights (constant over t)
__device__ float g_G[(size_t)MBIG * NG];              // precomputed input gates [t*Bsz+b][n], ~201MB
__device__ float g_gates[Bsz * NG];                   // per-step gates scratch
__device__ float g_h[Bsz * Hn];
__device__ float g_c[Bsz * Hn];

// ---------------- kernel 0: zero h, c ----------------
__global__ void k_zero() {
    int i = blockIdx.x * blockDim.x + threadIdx.x;
    if (i < Bsz * Hn) { g_h[i] = 0.f; g_c[i] = 0.f; }
}

// ---------------- kernel 1: a[b,d] = softmax_d( sum_{t,f} x[b,t,d,f] * w_x[f*T+t] ) ----------
// (attn_b and the recurrent scalar shifts are softmax-invariant -> dropped)
__global__ void k_softmax(const float* __restrict__ x, const float* __restrict__ attn_w) {
    __shared__ float w_s[Fn * Tn];   // 768
    __shared__ float red[Dn];
    int b = blockIdx.x;
    int d = threadIdx.x;             // 0..127

    for (int i = d; i < Fn * Tn; i += Dn) w_s[i] = attn_w[2 * Hn + i];
    __syncthreads();

    const float4* p = (const float4*)(x + ((size_t)b * Tn) * DF + d * Fn);
    float acc = 0.f;
    #pragma unroll 4
    for (int t = 0; t < Tn; t++) {
        float4 v0 = p[0], v1 = p[1], v2 = p[2], v3 = p[3];
        acc += v0.x * w_s[t]       + v0.y * w_s[48 + t]  + v0.z * w_s[96 + t]  + v0.w * w_s[144 + t]
             + v1.x * w_s[192 + t] + v1.y * w_s[240 + t] + v1.z * w_s[288 + t] + v1.w * w_s[336 + t]
             + v2.x * w_s[384 + t] + v2.y * w_s[432 + t] + v2.z * w_s[480 + t] + v2.w * w_s[528 + t]
             + v3.x * w_s[576 + t] + v3.y * w_s[624 + t] + v3.z * w_s[672 + t] + v3.w * w_s[720 + t];
        p += DF / 4;  // next t
    }

    // block softmax over 128 values
    red[d] = acc; __syncthreads();
    #pragma unroll
    for (int s = 64; s > 0; s >>= 1) {
        if (d < s) red[d] = fmaxf(red[d], red[d + s]);
        __syncthreads();
    }
    float mx = red[0]; __syncthreads();
    float e = expf(acc - mx);
    red[d] = e; __syncthreads();
    #pragma unroll
    for (int s = 64; s > 0; s >>= 1) {
        if (d < s) red[d] += red[d + s];
        __syncthreads();
    }
    g_a[b * Dn + d] = e / red[0];
}

// ---------------- kernel 2: big GEMM  G[m][n] = sum_k (a[b,k/16]*x[b,t,k]) * w_ih[n][k] + bias[n]
// m = t*Bsz + b  (so G is [T][B][NG], contiguous per step for the recurrence)
// 128x128 tile, BK=16, 256 threads, 8x8 per-thread microtile, fp32.
__global__ void __launch_bounds__(256, 2) k_gemm_big(
        const float* __restrict__ x, const float* __restrict__ w_ih,
        const float* __restrict__ b_ih, const float* __restrict__ b_hh) {
    __shared__ float As[16][132];
    __shared__ float Bs[16][132];

    int tid = threadIdx.x;
    int tx = tid & 15, ty = tid >> 4;
    int bm = blockIdx.y, bn = blockIdx.x;

    float acc[8][8];
    #pragma unroll
    for (int i = 0; i < 8; i++)
        #pragma unroll
        for (int j = 0; j < 8; j++) acc[i][j] = 0.f;

    int lin0 = tid * 4;

    for (int k0 = 0; k0 < DF; k0 += 16) {
        #pragma unroll
        for (int r = 0; r < 2; r++) {
            int linear = r * 1024 + lin0;      // 0..2044
            int mi = linear >> 4;              // row within tile (0..127)
            int ki = linear & 15;              // 0,4,8,12
            // A: x_hat row m = bm*128+mi  -> (b, t) gather, contiguous in k
            int m = bm * 128 + mi;
            int bb = m & 511, tt = m >> 9;
            float4 v = *(const float4*)(x + ((size_t)bb * Tn + tt) * DF + k0 + ki);
            float av = g_a[(bb << 7) + ((k0 + ki) >> 4)];   // a[b, d], d = k/16 (const over float4)
            As[ki + 0][mi] = v.x * av;
            As[ki + 1][mi] = v.y * av;
            As[ki + 2][mi] = v.z * av;
            As[ki + 3][mi] = v.w * av;
            // B: w_ih row n = bn*128+mi
            float4 w = *(const float4*)(w_ih + (size_t)(bn * 128 + mi) * DF + k0 + ki);
            Bs[ki + 0][mi] = w.x;
            Bs[ki + 1][mi] = w.y;
            Bs[ki + 2][mi] = w.z;
            Bs[ki + 3][mi] = w.w;
        }
        __syncthreads();

        #pragma unroll
        for (int kk = 0; kk < 16; kk++) {
            float4 a0 = *(const float4*)&As[kk][ty * 8];
            float4 a1 = *(const float4*)&As[kk][ty * 8 + 4];
            float4 b0 = *(const float4*)&Bs[kk][tx * 8];
            float4 b1 = *(const float4*)&Bs[kk][tx * 8 + 4];
            float af[8] = {a0.x, a0.y, a0.z, a0.w, a1.x, a1.y, a1.z, a1.w};
            float bf[8] = {b0.x, b0.y, b0.z, b0.w, b1.x, b1.y, b1.z, b1.w};
            #pragma unroll
            for (int i = 0; i < 8; i++)
                #pragma unroll
                for (int j = 0; j < 8; j++)
                    acc[i][j] += af[i] * bf[j];
        }
        __syncthreads();
    }

    // epilogue: + (b_ih + b_hh)
    int n0 = bn * 128 + tx * 8;
    float4 bi0 = *(const float4*)(b_ih + n0);
    float4 bi1 = *(const float4*)(b_ih + n0 + 4);
    float4 bh0 = *(const float4*)(b_hh + n0);
    float4 bh1 = *(const float4*)(b_hh + n0 + 4);
    float bias[8] = {bi0.x + bh0.x, bi0.y + bh0.y, bi0.z + bh0.z, bi0.w + bh0.w,
                     bi1.x + bh1.x, bi1.y + bh1.y, bi1.z + bh1.z, bi1.w + bh1.w};
    #pragma unroll
    for (int i = 0; i < 8; i++) {
        size_t m = (size_t)bm * 128 + ty * 8 + i;
        float4 o0 = make_float4(acc[i][0] + bias[0], acc[i][1] + bias[1],
                                acc[i][2] + bias[2], acc[i][3] + bias[3]);
        float4 o1 = make_float4(acc[i][4] + bias[4], acc[i][5] + bias[5],
                                acc[i][6] + bias[6], acc[i][7] + bias[7]);
        *(float4*)(g_G + m * NG + n0)     = o0;
        *(float4*)(g_G + m * NG + n0 + 4) = o1;
    }
}

// ---------------- kernel 3: per-step recurrent GEMM: gates = G[t] + h @ w_hh^T
// M=512(b), N=2048(n), K=512. 64x64 tile, BK=16, 256 threads, 4x4 per thread.
__global__ void __launch_bounds__(256) k_gemm_rec(const float* __restrict__ w_hh, int t) {
    __shared__ float As[16][68];
    __shared__ float Bs[16][68];

    int tid = threadIdx.x;
    int tx = tid & 15, ty = tid >> 4;
    int bm = blockIdx.y, bn = blockIdx.x;

    float acc[4][4];
    #pragma unroll
    for (int i = 0; i < 4; i++)
        #pragma unroll
        for (int j = 0; j < 4; j++) acc[i][j] = 0.f;

    int mi = tid >> 2;             // 0..63
    int ki = (tid & 3) * 4;        // 0,4,8,12

    for (int k0 = 0; k0 < Hn; k0 += 16) {
        float4 v = *(const float4*)(g_h + (bm * 64 + mi) * Hn + k0 + ki);
        As[ki + 0][mi] = v.x; As[ki + 1][mi] = v.y; As[ki + 2][mi] = v.z; As[ki + 3][mi] = v.w;
        float4 w = *(const float4*)(w_hh + (size_t)(bn * 64 + mi) * Hn + k0 + ki);
        Bs[ki + 0][mi] = w.x; Bs[ki + 1][mi] = w.y; Bs[ki + 2][mi] = w.z; Bs[ki + 3][mi] = w.w;
        __syncthreads();

        #pragma unroll
        for (int kk = 0; kk < 16; kk++) {
            float4 a = *(const float4*)&As[kk][ty * 4];
            float4 b = *(const float4*)&Bs[kk][tx * 4];
            float af[4] = {a.x, a.y, a.z, a.w};
            float bf[4] = {b.x, b.y, b.z, b.w};
            #pragma unroll
            for (int i = 0; i < 4; i++)
                #pragma unroll
                for (int j = 0; j < 4; j++)
                    acc[i][j] += af[i] * bf[j];
        }
        __syncthreads();
    }

    int n0 = bn * 64 + tx * 4;
    #pragma unroll
    for (int i = 0; i < 4; i++) {
        int b = bm * 64 + ty * 4 + i;
        float4 g = *(const float4*)(g_G + ((size_t)t * Bsz + b) * NG + n0);
        float4 o = make_float4(acc[i][0] + g.x, acc[i][1] + g.y,
                               acc[i][2] + g.z, acc[i][3] + g.w);
        *(float4*)(g_gates + (size_t)b * NG + n0) = o;
    }
}

// ---------------- kernel 4: pointwise LSTM update + output write ----------------
__global__ void k_lstm(float* __restrict__ out, int t) {
    int idx = blockIdx.x * blockDim.x + threadIdx.x;  // 0..262143
    int b = idx >> 9, j = idx & 511;
    const float* gr = g_gates + (size_t)b * NG;
    float gi = gr[j];
    float gf = gr[j + 512];
    float gg = gr[j + 1024];
    float go = gr[j + 1536];
    float c  = g_c[idx];
    float si = 1.f / (1.f + expf(-gi));
    float sf = 1.f / (1.f + expf(-gf));
    float so = 1.f / (1.f + expf(-go));
    float cn = sf * c + si * tanhf(gg);
    float hn = so * tanhf(cn);
    g_c[idx] = cn;
    g_h[idx] = hn;
    out[((size_t)b * Tn + t) * Hn + j] = hn;
}

// ---------------- launch ----------------
extern "C" void kernel_launch(void* const* d_in, const int* in_sizes, int n_in,
                              void* d_out, int out_size) {
    const float* input  = (const float*)d_in[0];  // (B,T,D,F)
    const float* attn_w = (const float*)d_in[1];  // (2H + F*T,)
    // d_in[2] = attn_b : softmax-invariant, unused
    const float* w_ih   = (const float*)d_in[3];  // (4H, D*F)
    const float* w_hh   = (const float*)d_in[4];  // (4H, H)
    const float* b_ih   = (const float*)d_in[5];
    const float* b_hh   = (const float*)d_in[6];
    float* out = (float*)d_out;                   // (B, T, H)

    k_zero<<<(Bsz * Hn + 255) / 256, 256>>>();
    k_softmax<<<Bsz, Dn>>>(input, attn_w);
    k_gemm_big<<<dim3(NG / 128, MBIG / 128), 256>>>(input, w_ih, b_ih, b_hh);

    for (int t = 0; t < Tn; t++) {
        k_gemm_rec<<<dim3(NG / 64, Bsz / 64), 256>>>(w_hh, t);
        k_lstm<<<(Bsz * Hn) / 256, 256>>>(out, t);
    }
}